// round 15
// baseline (speedup 1.0000x reference)
#include <cuda_runtime.h>
#include <math.h>

#define BG     256
#define NPG    512
#define EPG    8192
#define DF     128
#define CH     32
#define DFEAT  97
#define GSTR   100                     // g_feat row stride (16B-aligned slices)
#define TOPK   64
#define NTH    512
#define NW     16

#define BUF_STRIDE 33
#define SZ_BUF   (NPG*BUF_STRIDE)      // 16896 floats (single lin buffer)
#define SZ_WSM   4288
#define W0_STRIDE 132
#define W0_BIAS  (CH*W0_STRIDE)        // 4224
#define W36_BIAS (CH*36)               // 1152 (layers 1/2, stride-36 rows)
#define C1_STR   100                   // conv1 weight stride (padded)
#define C1_BIAS  1600                  // 16*100
#define C2W_OFF  1664
#define C2B_OFF  4224

typedef unsigned long long ull;

// scratch: concat feature [N, 100] (stride 100, 97 used)
__device__ float g_feat[(size_t)BG * NPG * GSTR];

#define SMEM_FLOATS (SZ_BUF + SZ_WSM + NPG + NPG)          // bufL, Wsm, norm, key
#define SMEM_INTS   (NPG + (NPG+2) + NPG)                  // idx, row_off(+pad), tmp
#define SMEM_BYTES  (SMEM_FLOATS*4 + SMEM_INTS*4 + EPG*2 + 16)

__global__ void __launch_bounds__(NTH, 2)
dgcnn_kernel(const float* __restrict__ x,
             const float* __restrict__ W0, const float* __restrict__ b0,
             const float* __restrict__ W1, const float* __restrict__ b1,
             const float* __restrict__ W2, const float* __restrict__ b2,
             const float* __restrict__ W3, const float* __restrict__ b3,
             const float* __restrict__ c1w, const float* __restrict__ c1b,
             const float* __restrict__ c2w, const float* __restrict__ c2b,
             const float* __restrict__ d1w, const float* __restrict__ d1b,
             const float* __restrict__ d2w, const float* __restrict__ d2b,
             const int* __restrict__ esrc, const int* __restrict__ edst,
             float* __restrict__ out)
{
    extern __shared__ float sm[];
    float* bufL   = sm;                      // [512][33]: lin (cols 0-31), lin3 (col 32)
    float* Wsm    = bufL + SZ_BUF;
    float* norm_s = Wsm + SZ_WSM;
    float* key_s  = norm_s + NPG;            // low half of packed sort array
    int*   idx_s  = (int*)(key_s + NPG);     // high half of packed sort array
    ull*   pak_s  = (ull*)key_s;             // 512 x 8B aliasing key_s+idx_s
    int*   row_off= idx_s + NPG;
    int*   tmp_i  = row_off + NPG + 2;       // +2: keeps csr 8B-aligned
    unsigned short* csr = (unsigned short*)(tmp_i + NPG);

    const int g    = blockIdx.x;
    const int tid  = threadIdx.x;
    const int lane = tid & 31;
    const int wid  = tid >> 5;
    const int off  = g * NPG;
    const int* es  = esrc + g * EPG;
    const int* ed  = edst + g * EPG;
    float* gf = g_feat + (size_t)off * GSTR;

    // ================= degree counts (src for norm, dst for CSR) =============
    tmp_i[tid] = 0;
    idx_s[tid] = 0;
    __syncthreads();
    for (int e = tid; e < EPG; e += NTH) {
        atomicAdd(&tmp_i[es[e] - off], 1);
        atomicAdd(&idx_s[ed[e] - off], 1);
    }
    __syncthreads();
    norm_s[tid] = 1.0f / (float)(1 + tmp_i[tid]);   // +1 self loop
    const int dcnt = idx_s[tid];
    __syncthreads();

    // exclusive scan of dst in-counts -> row_off
    {
        int v = dcnt;
        #pragma unroll
        for (int o = 1; o < 32; o <<= 1) {
            int nn = __shfl_up_sync(0xffffffffu, v, o);
            if (lane >= o) v += nn;
        }
        if (lane == 31) key_s[wid] = __int_as_float(v);
        __syncthreads();
        if (wid == 0 && lane < NW) {
            int t = __float_as_int(key_s[lane]);
            int w = t;
            #pragma unroll
            for (int o = 1; o < NW; o <<= 1) {
                int nn = __shfl_up_sync(0x0000ffffu, w, o);
                if (lane >= o) w += nn;
            }
            key_s[lane] = __int_as_float(w - t);
        }
        __syncthreads();
        int ro = (v - dcnt) + __float_as_int(key_s[wid]);
        row_off[tid] = ro;
        tmp_i[tid] = ro;                    // cursor
        if (tid == 0) row_off[NPG] = EPG;
        __syncthreads();
    }

    // CSR fill — store PRE-SCALED index (src*BUF_STRIDE; max 511*33=16863 < 64K)
    for (int e = tid; e < EPG; e += NTH) {
        int d = ed[e] - off;
        int p = atomicAdd(&tmp_i[d], 1);
        csr[p] = (unsigned short)((es[e] - off) * BUF_STRIDE);
    }

    // ================= layer 0: lin = x @ W0^T + b0 ===========================
    for (int j = tid; j < CH * DF; j += NTH) {
        int r = j >> 7, c = j & 127;
        Wsm[r * W0_STRIDE + c] = W0[j];
    }
    if (tid < CH) Wsm[W0_BIAS + tid] = b0[tid];
    __syncthreads();

    {
        const float bias = Wsm[W0_BIAS + lane];
        const float* wr = Wsm + lane * W0_STRIDE;
        #pragma unroll 1
        for (int m = 0; m < 4; m++) {
            const int n0 = m * 128 + wid * 8;         // 8 consecutive nodes
            const float* xb = x + (size_t)(off + n0) * DF;
            float a0 = bias, a1 = bias, a2 = bias, a3 = bias;
            float a4 = bias, a5 = bias, a6 = bias, a7 = bias;
            #pragma unroll 2
            for (int c = 0; c < DF; c += 4) {
                float4 wv = *(const float4*)(wr + c);
                float4 v;
                v = __ldg((const float4*)(xb + c         )); a0 += v.x*wv.x + v.y*wv.y + v.z*wv.z + v.w*wv.w;
                v = __ldg((const float4*)(xb + c + 1*DF  )); a1 += v.x*wv.x + v.y*wv.y + v.z*wv.z + v.w*wv.w;
                v = __ldg((const float4*)(xb + c + 2*DF  )); a2 += v.x*wv.x + v.y*wv.y + v.z*wv.z + v.w*wv.w;
                v = __ldg((const float4*)(xb + c + 3*DF  )); a3 += v.x*wv.x + v.y*wv.y + v.z*wv.z + v.w*wv.w;
                v = __ldg((const float4*)(xb + c + 4*DF  )); a4 += v.x*wv.x + v.y*wv.y + v.z*wv.z + v.w*wv.w;
                v = __ldg((const float4*)(xb + c + 5*DF  )); a5 += v.x*wv.x + v.y*wv.y + v.z*wv.z + v.w*wv.w;
                v = __ldg((const float4*)(xb + c + 6*DF  )); a6 += v.x*wv.x + v.y*wv.y + v.z*wv.z + v.w*wv.w;
                v = __ldg((const float4*)(xb + c + 7*DF  )); a7 += v.x*wv.x + v.y*wv.y + v.z*wv.z + v.w*wv.w;
            }
            float* ob = bufL + n0 * BUF_STRIDE + lane;
            ob[0*BUF_STRIDE] = a0; ob[1*BUF_STRIDE] = a1;
            ob[2*BUF_STRIDE] = a2; ob[3*BUF_STRIDE] = a3;
            ob[4*BUF_STRIDE] = a4; ob[5*BUF_STRIDE] = a5;
            ob[6*BUF_STRIDE] = a6; ob[7*BUF_STRIDE] = a7;
        }
    }
    __syncthreads();

    // aggregate: h[i] = tanh(norm[i]*(lin[i]+sum lin[src])) -> g_feat only
    // 4-way gather, one 8-byte uniform index load; indices pre-scaled (*33)
    auto AGG32 = [&](int fc) {
        const float* bl = bufL + lane;
        for (int n = wid; n < NPG; n += NW) {
            float s = bl[n * BUF_STRIDE];
            int e  = row_off[n];
            const int e1 = row_off[n + 1];
            while (e < e1 && (e & 3)) {
                s += bl[(int)csr[e]];
                e++;
            }
            float s2 = 0.0f, s3 = 0.0f, s4 = 0.0f;
            for (; e + 4 <= e1; e += 4) {
                ull p = *(const ull*)(csr + e);
                s  += bl[(int)( p        & 0xffffu)];
                s2 += bl[(int)((p >> 16) & 0xffffu)];
                s3 += bl[(int)((p >> 32) & 0xffffu)];
                s4 += bl[(int)( p >> 48          )];
            }
            for (; e < e1; e++)
                s += bl[(int)csr[e]];
            s += (s2 + s3) + s4;
            s = tanhf(s * norm_s[n]);
            gf[(size_t)n * GSTR + fc + lane] = s;
        }
        __syncthreads();
    };
    AGG32(0);

    // == layers 1, 2 (32->32): smem weights + float4 h broadcasts, 8 nodes ====
    #pragma unroll 1
    for (int L = 1; L <= 2; L++) {
        const float* Wg = (L == 1) ? W1 : W2;
        const float* bg = (L == 1) ? b1 : b2;
        const int fcin = 32 * (L - 1);

        for (int j = tid; j < CH * CH; j += NTH) {
            int r = j >> 5, c = j & 31;
            Wsm[r * 36 + c] = Wg[j];
        }
        if (tid < CH) Wsm[W36_BIAS + tid] = bg[tid];
        __syncthreads();

        const float bias = Wsm[W36_BIAS + lane];
        const float* wr = Wsm + lane * 36;
        #pragma unroll 1
        for (int m = 0; m < 4; m++) {
            const int n0 = m * 128 + wid * 8;
            const float* hb = gf + (size_t)n0 * GSTR + fcin;
            float a0 = bias, a1 = bias, a2 = bias, a3 = bias;
            float a4 = bias, a5 = bias, a6 = bias, a7 = bias;
            #pragma unroll
            for (int cc = 0; cc < 8; cc++) {
                float4 wv = *(const float4*)(wr + 4 * cc);
                float4 v;
                v = __ldg((const float4*)(hb + 4*cc         )); a0 += v.x*wv.x + v.y*wv.y + v.z*wv.z + v.w*wv.w;
                v = __ldg((const float4*)(hb + 4*cc + 1*GSTR)); a1 += v.x*wv.x + v.y*wv.y + v.z*wv.z + v.w*wv.w;
                v = __ldg((const float4*)(hb + 4*cc + 2*GSTR)); a2 += v.x*wv.x + v.y*wv.y + v.z*wv.z + v.w*wv.w;
                v = __ldg((const float4*)(hb + 4*cc + 3*GSTR)); a3 += v.x*wv.x + v.y*wv.y + v.z*wv.z + v.w*wv.w;
                v = __ldg((const float4*)(hb + 4*cc + 4*GSTR)); a4 += v.x*wv.x + v.y*wv.y + v.z*wv.z + v.w*wv.w;
                v = __ldg((const float4*)(hb + 4*cc + 5*GSTR)); a5 += v.x*wv.x + v.y*wv.y + v.z*wv.z + v.w*wv.w;
                v = __ldg((const float4*)(hb + 4*cc + 6*GSTR)); a6 += v.x*wv.x + v.y*wv.y + v.z*wv.z + v.w*wv.w;
                v = __ldg((const float4*)(hb + 4*cc + 7*GSTR)); a7 += v.x*wv.x + v.y*wv.y + v.z*wv.z + v.w*wv.w;
            }
            float* ob = bufL + n0 * BUF_STRIDE + lane;
            ob[0*BUF_STRIDE] = a0; ob[1*BUF_STRIDE] = a1;
            ob[2*BUF_STRIDE] = a2; ob[3*BUF_STRIDE] = a3;
            ob[4*BUF_STRIDE] = a4; ob[5*BUF_STRIDE] = a5;
            ob[6*BUF_STRIDE] = a6; ob[7*BUF_STRIDE] = a7;
        }
        __syncthreads();
        AGG32(32 * L);
    }

    // == layer 3 (32 -> 1): warp-per-node, shfl reduce; result -> bufL col 32 ==
    {
        const float w3v = __ldg(W3 + lane);
        const float b3v = __ldg(b3);
        for (int i = 0; i < NPG / NW; i++) {
            const int n = wid * (NPG / NW) + i;
            float acc = gf[(size_t)n * GSTR + 64 + lane] * w3v;
            #pragma unroll
            for (int o = 16; o > 0; o >>= 1)
                acc += __shfl_down_sync(0xffffffffu, acc, o);
            if (lane == 0) bufL[n * BUF_STRIDE + 32] = acc + b3v;
        }
    }
    __syncthreads();

    // key aggregation (per-thread node); gathers use pre-scaled idx (+32 col)
    ull preg;
    {
        const float* bl32 = bufL + 32;
        float s = bl32[tid * BUF_STRIDE];
        const int e1 = row_off[tid + 1];
        for (int e = row_off[tid]; e < e1; e++)
            s += bl32[(int)csr[e]];
        s = tanhf(s * norm_s[tid]);
        gf[(size_t)tid * GSTR + 96] = s;
        // order-preserving float->uint map (ascending), inverted for descending
        unsigned int b = __float_as_uint(s);
        unsigned int mapped = b ^ (((int)b >> 31) | 0x80000000u);
        preg = ((ull)(~mapped) << 32) | (unsigned int)tid;
    }

    // conv1/conv2 weights -> smem now (overlaps the sort; consumed after it)
    for (int j = tid; j < 16 * DFEAT; j += NTH) {
        int o = j / DFEAT, d = j - o * DFEAT;
        Wsm[o * C1_STR + d] = c1w[j];
    }
    if (tid < 16) Wsm[C1_BIAS + tid] = c1b[tid];
    for (int j = tid; j < 32 * 16 * 5; j += NTH) Wsm[C2W_OFF + j] = c2w[j];
    if (tid < 32) Wsm[C2B_OFF + tid] = c2b[tid];
    __syncthreads();

    // ==== bitonic sort (ascending on packed u64): shfl j<32, smem j>=32 ======
    for (int k = 2; k <= NPG; k <<= 1) {
        for (int j = k >> 1; j > 0; j >>= 1) {
            const bool up    = ((tid & k) == 0);
            const bool lower = ((tid & j) == 0);
            ull pp;
            if (j >= 32) {
                pak_s[tid] = preg;
                __syncthreads();
                pp = pak_s[tid ^ j];
                __syncthreads();
            } else {
                pp = __shfl_xor_sync(0xffffffffu, preg, j);
            }
            bool ownBetter = preg < pp;          // ascending packed order
            bool takePartner = (up ^ lower) ? ownBetter : !ownBetter;
            if (takePartner) preg = pp;
        }
    }
    idx_s[tid] = (int)(unsigned int)(preg & 0xffffffffu);
    __syncthreads();

    // ================= gather top-K feature rows (stride 100) =================
    float* t64 = bufL;                 // 64*100 = 6400 floats
    for (int j = tid; j < TOPK * DFEAT; j += NTH) {
        int kk = j / DFEAT, d = j - kk * DFEAT;
        t64[kk * C1_STR + d] = gf[(size_t)idx_s[kk] * GSTR + d];
    }
    __syncthreads();

    float* c1o  = bufL + 6400;   // 1024
    float* pool = bufL + 7424;   // 512
    float* flat = bufL + 7936;   // 896
    float* hid  = bufL + 8832;   // 128

    // conv1 (per-node linear over D=97) + relu — float4 over 96, +1 scalar
    #pragma unroll
    for (int it = 0; it < 2; it++) {
        int j = tid + it * NTH;
        int o = j >> 6, kk = j & 63;
        const float* tr = t64 + kk * C1_STR;
        const float* wr = Wsm + o * C1_STR;
        float acc = Wsm[C1_BIAS + o];
        #pragma unroll 4
        for (int d = 0; d < 96; d += 4) {
            float4 a = *(const float4*)(tr + d);
            float4 b = *(const float4*)(wr + d);
            acc += a.x*b.x + a.y*b.y + a.z*b.z + a.w*b.w;
        }
        acc += tr[96] * wr[96];
        c1o[j] = fmaxf(acc, 0.0f);
    }
    __syncthreads();
    // maxpool(2)
    if (tid < 16 * 32) {
        int o = tid >> 5, j2 = tid & 31;
        pool[tid] = fmaxf(c1o[o * 64 + 2 * j2], c1o[o * 64 + 2 * j2 + 1]);
    }
    __syncthreads();
    // conv2 (16->32, k=5, valid) + relu, flat index = o*28 + t
    #pragma unroll
    for (int it = 0; it < 2; it++) {
        int j = tid + it * NTH;
        if (j < 896) {
            int o = j / 28, t = j - o * 28;
            const float* wo = Wsm + C2W_OFF + o * 80;
            const float* pb = pool + t;
            float acc = Wsm[C2B_OFF + o];
            #pragma unroll
            for (int i = 0; i < 16; i++) {
                #pragma unroll
                for (int kk = 0; kk < 5; kk++)
                    acc += pb[i * 32 + kk] * wo[i * 5 + kk];
            }
            flat[j] = fmaxf(acc, 0.0f);
        }
    }
    __syncthreads();

    // dense 896 -> 128, relu  (warp per output row)
    for (int h = wid; h < 128; h += NW) {
        const float* wr = d1w + (size_t)h * 896;
        float acc = 0.0f;
        for (int m = lane; m < 896; m += 32) acc += flat[m] * wr[m];
        #pragma unroll
        for (int o = 16; o > 0; o >>= 1) acc += __shfl_down_sync(0xffffffffu, acc, o);
        if (lane == 0) hid[h] = fmaxf(acc + d1b[h], 0.0f);
    }
    __syncthreads();

    // dense 128 -> 10
    if (wid < 10) {
        const float* wr = d2w + wid * 128;
        float acc = 0.0f;
        for (int m = lane; m < 128; m += 32) acc += hid[m] * wr[m];
        #pragma unroll
        for (int o = 16; o > 0; o >>= 1) acc += __shfl_down_sync(0xffffffffu, acc, o);
        if (lane == 0) out[g * 10 + wid] = acc + d2b[wid];
    }
}

extern "C" void kernel_launch(void* const* d_in, const int* in_sizes, int n_in,
                              void* d_out, int out_size)
{
    (void)in_sizes; (void)n_in; (void)out_size;
    const float* x    = (const float*)d_in[0];
    const float* W0   = (const float*)d_in[1];
    const float* b0   = (const float*)d_in[2];
    const float* W1   = (const float*)d_in[3];
    const float* b1   = (const float*)d_in[4];
    const float* W2   = (const float*)d_in[5];
    const float* b2   = (const float*)d_in[6];
    const float* W3   = (const float*)d_in[7];
    const float* b3   = (const float*)d_in[8];
    const float* c1w  = (const float*)d_in[9];
    const float* c1b  = (const float*)d_in[10];
    const float* c2w  = (const float*)d_in[11];
    const float* c2b  = (const float*)d_in[12];
    const float* d1w  = (const float*)d_in[13];
    const float* d1b  = (const float*)d_in[14];
    const float* d2w  = (const float*)d_in[15];
    const float* d2b  = (const float*)d_in[16];
    const int*   esrc = (const int*)d_in[17];
    const int*   edst = (const int*)d_in[18];
    float* out = (float*)d_out;

    cudaFuncSetAttribute(dgcnn_kernel,
                         cudaFuncAttributeMaxDynamicSharedMemorySize, SMEM_BYTES);
    dgcnn_kernel<<<BG, NTH, SMEM_BYTES>>>(x, W0, b0, W1, b1, W2, b2, W3, b3,
                                          c1w, c1b, c2w, c2b,
                                          d1w, d1b, d2w, d2b,
                                          esrc, edst, out);
}

// round 17
// speedup vs baseline: 1.0894x; 1.0894x over previous
#include <cuda_runtime.h>
#include <math.h>

#define BG     256
#define NPG    512
#define EPG    8192
#define DF     128
#define CH     32
#define DFEAT  97
#define GSTR   100                     // g_feat row stride (16B-aligned slices)
#define TOPK   64
#define NTH    512
#define NW     16

#define BUF_STRIDE 33
#define ZROW   512                     // zero row index (gathers add 0)
#define SZ_BUF (((513*BUF_STRIDE)+3)&~3)   // 16932 floats -> keeps Wsm 16B-aligned
#define SZ_WSM   4288
#define W0_STRIDE 132
#define W0_BIAS  (CH*W0_STRIDE)        // 4224
#define W36_BIAS (CH*36)               // 1152 (layers 1/2, stride-36 rows)
#define C1_STR   100                   // conv1 weight stride (padded)
#define C1_BIAS  1600                  // 16*100
#define C2W_OFF  1664
#define C2B_OFF  4224
#define CSR_CAP  (EPG + 3*NPG + 8)     // padded rows + overread pad

typedef unsigned long long ull;

// scratch: concat feature [N, 100] (stride 100, 97 used)
__device__ float g_feat[(size_t)BG * NPG * GSTR];

#define SMEM_FLOATS (SZ_BUF + SZ_WSM + NPG + NPG)          // bufL, Wsm, norm, key
#define SMEM_INTS   (NPG + (NPG+2) + (NPG+2))              // idx, row_off, tmp/lin3
#define SMEM_BYTES  (SMEM_FLOATS*4 + SMEM_INTS*4 + CSR_CAP*2)

__global__ void __launch_bounds__(NTH, 2)
dgcnn_kernel(const float* __restrict__ x,
             const float* __restrict__ W0, const float* __restrict__ b0,
             const float* __restrict__ W1, const float* __restrict__ b1,
             const float* __restrict__ W2, const float* __restrict__ b2,
             const float* __restrict__ W3, const float* __restrict__ b3,
             const float* __restrict__ c1w, const float* __restrict__ c1b,
             const float* __restrict__ c2w, const float* __restrict__ c2b,
             const float* __restrict__ d1w, const float* __restrict__ d1b,
             const float* __restrict__ d2w, const float* __restrict__ d2b,
             const int* __restrict__ esrc, const int* __restrict__ edst,
             float* __restrict__ out)
{
    extern __shared__ float sm[];
    float* bufL   = sm;                      // [513][33]: rows 0-511 lin, row 512 zeros
    float* Wsm    = bufL + SZ_BUF;           // 16B aligned
    float* norm_s = Wsm + SZ_WSM;
    float* key_s  = norm_s + NPG;            // low half of packed sort array (8B aligned)
    int*   idx_s  = (int*)(key_s + NPG);     // high half of packed sort array
    ull*   pak_s  = (ull*)key_s;             // 512 x 8B aliasing key_s+idx_s
    int*   row_off= idx_s + NPG;             // 513 + 1 pad
    int*   tmp_i  = row_off + NPG + 2;       // 513 + 1 pad (also lin3)
    unsigned short* csr = (unsigned short*)(tmp_i + NPG + 2);  // 8B aligned
    float* lin3_s = (float*)tmp_i;           // reuse after CSR fill (513 slots)

    const int g    = blockIdx.x;
    const int tid  = threadIdx.x;
    const int lane = tid & 31;
    const int wid  = tid >> 5;
    const int off  = g * NPG;
    const int* es  = esrc + g * EPG;
    const int* ed  = edst + g * EPG;
    float* gf = g_feat + (size_t)off * GSTR;

    // ================= degree counts (src for norm, dst for CSR) =============
    tmp_i[tid] = 0;
    idx_s[tid] = 0;
    __syncthreads();
    for (int e = tid; e < EPG; e += NTH) {
        atomicAdd(&tmp_i[es[e] - off], 1);
        atomicAdd(&idx_s[ed[e] - off], 1);
    }
    __syncthreads();
    norm_s[tid] = 1.0f / (float)(1 + tmp_i[tid]);   // +1 self loop
    const int dcnt = idx_s[tid];
    const int pcnt = (dcnt + 3) & ~3;               // padded to multiple of 4
    __syncthreads();

    // exclusive scan of PADDED in-counts -> row_off (all multiples of 4)
    int my_ro;
    {
        int v = pcnt;
        #pragma unroll
        for (int o = 1; o < 32; o <<= 1) {
            int nn = __shfl_up_sync(0xffffffffu, v, o);
            if (lane >= o) v += nn;
        }
        if (lane == 31) key_s[wid] = __int_as_float(v);
        __syncthreads();
        if (wid == 0 && lane < NW) {
            int t = __float_as_int(key_s[lane]);
            int w = t;
            #pragma unroll
            for (int o = 1; o < NW; o <<= 1) {
                int nn = __shfl_up_sync(0x0000ffffu, w, o);
                if (lane >= o) w += nn;
            }
            key_s[lane] = __int_as_float(w - t);
        }
        __syncthreads();
        my_ro = (v - pcnt) + __float_as_int(key_s[wid]);
        row_off[tid] = my_ro;
        tmp_i[tid] = my_ro;                 // cursor
        if (tid == NPG - 1) row_off[NPG] = my_ro + pcnt;
        __syncthreads();
    }

    // CSR fill (by dst; row order irrelevant — it's a sum)
    for (int e = tid; e < EPG; e += NTH) {
        int d = ed[e] - off;
        int p = atomicAdd(&tmp_i[d], 1);
        csr[p] = (unsigned short)(es[e] - off);
    }
    // pad own row with zero-row edges (slots disjoint from real fills)
    for (int p = my_ro + dcnt; p < my_ro + pcnt; p++)
        csr[p] = (unsigned short)ZROW;
    // zero the dummy row of bufL (never written by GEMMs)
    if (tid < BUF_STRIDE) bufL[ZROW * BUF_STRIDE + tid] = 0.0f;

    // ================= layer 0: lin = x @ W0^T + b0 ===========================
    for (int j = tid; j < CH * DF; j += NTH) {
        int r = j >> 7, c = j & 127;
        Wsm[r * W0_STRIDE + c] = W0[j];
    }
    if (tid < CH) Wsm[W0_BIAS + tid] = b0[tid];
    __syncthreads();

    {
        const float bias = Wsm[W0_BIAS + lane];
        const float* wr = Wsm + lane * W0_STRIDE;
        #pragma unroll 1
        for (int m = 0; m < 4; m++) {
            const int n0 = m * 128 + wid * 8;         // 8 consecutive nodes
            const float* xb = x + (size_t)(off + n0) * DF;
            float a0 = bias, a1 = bias, a2 = bias, a3 = bias;
            float a4 = bias, a5 = bias, a6 = bias, a7 = bias;
            #pragma unroll 2
            for (int c = 0; c < DF; c += 4) {
                float4 wv = *(const float4*)(wr + c);
                float4 v;
                v = __ldg((const float4*)(xb + c         )); a0 += v.x*wv.x + v.y*wv.y + v.z*wv.z + v.w*wv.w;
                v = __ldg((const float4*)(xb + c + 1*DF  )); a1 += v.x*wv.x + v.y*wv.y + v.z*wv.z + v.w*wv.w;
                v = __ldg((const float4*)(xb + c + 2*DF  )); a2 += v.x*wv.x + v.y*wv.y + v.z*wv.z + v.w*wv.w;
                v = __ldg((const float4*)(xb + c + 3*DF  )); a3 += v.x*wv.x + v.y*wv.y + v.z*wv.z + v.w*wv.w;
                v = __ldg((const float4*)(xb + c + 4*DF  )); a4 += v.x*wv.x + v.y*wv.y + v.z*wv.z + v.w*wv.w;
                v = __ldg((const float4*)(xb + c + 5*DF  )); a5 += v.x*wv.x + v.y*wv.y + v.z*wv.z + v.w*wv.w;
                v = __ldg((const float4*)(xb + c + 6*DF  )); a6 += v.x*wv.x + v.y*wv.y + v.z*wv.z + v.w*wv.w;
                v = __ldg((const float4*)(xb + c + 7*DF  )); a7 += v.x*wv.x + v.y*wv.y + v.z*wv.z + v.w*wv.w;
            }
            float* ob = bufL + n0 * BUF_STRIDE + lane;
            ob[0*BUF_STRIDE] = a0; ob[1*BUF_STRIDE] = a1;
            ob[2*BUF_STRIDE] = a2; ob[3*BUF_STRIDE] = a3;
            ob[4*BUF_STRIDE] = a4; ob[5*BUF_STRIDE] = a5;
            ob[6*BUF_STRIDE] = a6; ob[7*BUF_STRIDE] = a7;
        }
    }
    __syncthreads();

    // aggregate: h[i] = tanh(norm[i]*(lin[i]+sum lin[src])) -> g_feat only
    // rows padded to multiples of 4: pure 4-way iterations, no head/tail
    auto AGG32 = [&](int fc) {
        const float* bl = bufL + lane;
        for (int n = wid; n < NPG; n += NW) {
            float s = bl[n * BUF_STRIDE];
            const int e1 = row_off[n + 1];
            float s2 = 0.0f, s3 = 0.0f, s4 = 0.0f;
            for (int e = row_off[n]; e < e1; e += 4) {
                ull p = *(const ull*)(csr + e);
                s  += bl[(int)( p        & 0xffffu) * BUF_STRIDE];
                s2 += bl[(int)((p >> 16) & 0xffffu) * BUF_STRIDE];
                s3 += bl[(int)((p >> 32) & 0xffffu) * BUF_STRIDE];
                s4 += bl[(int)( p >> 48          ) * BUF_STRIDE];
            }
            s += (s2 + s3) + s4;
            s = tanhf(s * norm_s[n]);
            gf[(size_t)n * GSTR + fc + lane] = s;
        }
        __syncthreads();
    };
    AGG32(0);

    // == layers 1, 2 (32->32): smem weights + float4 h broadcasts, 8 nodes ====
    #pragma unroll 1
    for (int L = 1; L <= 2; L++) {
        const float* Wg = (L == 1) ? W1 : W2;
        const float* bg = (L == 1) ? b1 : b2;
        const int fcin = 32 * (L - 1);

        for (int j = tid; j < CH * CH; j += NTH) {
            int r = j >> 5, c = j & 31;
            Wsm[r * 36 + c] = Wg[j];
        }
        if (tid < CH) Wsm[W36_BIAS + tid] = bg[tid];
        __syncthreads();

        const float bias = Wsm[W36_BIAS + lane];
        const float* wr = Wsm + lane * 36;
        #pragma unroll 1
        for (int m = 0; m < 4; m++) {
            const int n0 = m * 128 + wid * 8;
            const float* hb = gf + (size_t)n0 * GSTR + fcin;
            float a0 = bias, a1 = bias, a2 = bias, a3 = bias;
            float a4 = bias, a5 = bias, a6 = bias, a7 = bias;
            #pragma unroll
            for (int cc = 0; cc < 8; cc++) {
                float4 wv = *(const float4*)(wr + 4 * cc);
                float4 v;
                v = __ldg((const float4*)(hb + 4*cc         )); a0 += v.x*wv.x + v.y*wv.y + v.z*wv.z + v.w*wv.w;
                v = __ldg((const float4*)(hb + 4*cc + 1*GSTR)); a1 += v.x*wv.x + v.y*wv.y + v.z*wv.z + v.w*wv.w;
                v = __ldg((const float4*)(hb + 4*cc + 2*GSTR)); a2 += v.x*wv.x + v.y*wv.y + v.z*wv.z + v.w*wv.w;
                v = __ldg((const float4*)(hb + 4*cc + 3*GSTR)); a3 += v.x*wv.x + v.y*wv.y + v.z*wv.z + v.w*wv.w;
                v = __ldg((const float4*)(hb + 4*cc + 4*GSTR)); a4 += v.x*wv.x + v.y*wv.y + v.z*wv.z + v.w*wv.w;
                v = __ldg((const float4*)(hb + 4*cc + 5*GSTR)); a5 += v.x*wv.x + v.y*wv.y + v.z*wv.z + v.w*wv.w;
                v = __ldg((const float4*)(hb + 4*cc + 6*GSTR)); a6 += v.x*wv.x + v.y*wv.y + v.z*wv.z + v.w*wv.w;
                v = __ldg((const float4*)(hb + 4*cc + 7*GSTR)); a7 += v.x*wv.x + v.y*wv.y + v.z*wv.z + v.w*wv.w;
            }
            float* ob = bufL + n0 * BUF_STRIDE + lane;
            ob[0*BUF_STRIDE] = a0; ob[1*BUF_STRIDE] = a1;
            ob[2*BUF_STRIDE] = a2; ob[3*BUF_STRIDE] = a3;
            ob[4*BUF_STRIDE] = a4; ob[5*BUF_STRIDE] = a5;
            ob[6*BUF_STRIDE] = a6; ob[7*BUF_STRIDE] = a7;
        }
        __syncthreads();
        AGG32(32 * L);
    }

    // ============== layer 3 (32 -> 1): warp-per-node, shfl reduce =============
    {
        const float w3v = __ldg(W3 + lane);
        const float b3v = __ldg(b3);
        for (int i = 0; i < NPG / NW; i++) {
            const int n = wid * (NPG / NW) + i;
            float acc = gf[(size_t)n * GSTR + 64 + lane] * w3v;
            #pragma unroll
            for (int o = 16; o > 0; o >>= 1)
                acc += __shfl_down_sync(0xffffffffu, acc, o);
            if (lane == 0) lin3_s[n] = acc + b3v;
        }
        if (tid == 0) lin3_s[ZROW] = 0.0f;   // pad edges add 0
    }
    __syncthreads();

    // key aggregation (per-thread node); pack (desc-key, asc-idx) into one u64
    ull preg;
    {
        float s = lin3_s[tid];
        const int e1 = row_off[tid + 1];
        float s2 = 0.0f, s3 = 0.0f, s4 = 0.0f;
        for (int e = row_off[tid]; e < e1; e += 4) {
            ull p = *(const ull*)(csr + e);
            s  += lin3_s[(int)( p        & 0xffffu)];
            s2 += lin3_s[(int)((p >> 16) & 0xffffu)];
            s3 += lin3_s[(int)((p >> 32) & 0xffffu)];
            s4 += lin3_s[(int)( p >> 48          )];
        }
        s += (s2 + s3) + s4;
        s = tanhf(s * norm_s[tid]);
        gf[(size_t)tid * GSTR + 96] = s;
        // order-preserving float->uint map (ascending), inverted for descending
        unsigned int b = __float_as_uint(s);
        unsigned int mapped = b ^ (((int)b >> 31) | 0x80000000u);
        preg = ((ull)(~mapped) << 32) | (unsigned int)tid;
    }
    __syncthreads();

    // ==== bitonic sort (ascending on packed u64): shfl j<32, smem j>=32 ======
    for (int k = 2; k <= NPG; k <<= 1) {
        for (int j = k >> 1; j > 0; j >>= 1) {
            const bool up    = ((tid & k) == 0);
            const bool lower = ((tid & j) == 0);
            ull pp;
            if (j >= 32) {
                pak_s[tid] = preg;
                __syncthreads();
                pp = pak_s[tid ^ j];
                __syncthreads();
            } else {
                pp = __shfl_xor_sync(0xffffffffu, preg, j);
            }
            bool ownBetter = preg < pp;          // ascending packed order
            bool takePartner = (up ^ lower) ? ownBetter : !ownBetter;
            if (takePartner) preg = pp;
        }
    }
    idx_s[tid] = (int)(unsigned int)(preg & 0xffffffffu);
    __syncthreads();

    // ================= gather top-K feature rows (stride 100) =================
    float* t64 = bufL;                 // 64*100 = 6400 floats
    for (int j = tid; j < TOPK * DFEAT; j += NTH) {
        int kk = j / DFEAT, d = j - kk * DFEAT;
        t64[kk * C1_STR + d] = gf[(size_t)idx_s[kk] * GSTR + d];
    }
    // conv1 weights (stride 100) + conv2 weights into smem
    for (int j = tid; j < 16 * DFEAT; j += NTH) {
        int o = j / DFEAT, d = j - o * DFEAT;
        Wsm[o * C1_STR + d] = c1w[j];
    }
    if (tid < 16) Wsm[C1_BIAS + tid] = c1b[tid];
    for (int j = tid; j < 32 * 16 * 5; j += NTH) Wsm[C2W_OFF + j] = c2w[j];
    if (tid < 32) Wsm[C2B_OFF + tid] = c2b[tid];
    __syncthreads();

    float* c1o  = bufL + 6400;   // 1024
    float* pool = bufL + 7424;   // 512
    float* flat = bufL + 7936;   // 896
    float* hid  = bufL + 8832;   // 128

    // conv1 (per-node linear over D=97) + relu — float4 over 96, +1 scalar
    #pragma unroll
    for (int it = 0; it < 2; it++) {
        int j = tid + it * NTH;
        int o = j >> 6, kk = j & 63;
        const float* tr = t64 + kk * C1_STR;
        const float* wr = Wsm + o * C1_STR;
        float acc = Wsm[C1_BIAS + o];
        #pragma unroll 4
        for (int d = 0; d < 96; d += 4) {
            float4 a = *(const float4*)(tr + d);
            float4 b = *(const float4*)(wr + d);
            acc += a.x*b.x + a.y*b.y + a.z*b.z + a.w*b.w;
        }
        acc += tr[96] * wr[96];
        c1o[j] = fmaxf(acc, 0.0f);
    }
    __syncthreads();
    // maxpool(2)
    if (tid < 16 * 32) {
        int o = tid >> 5, j2 = tid & 31;
        pool[tid] = fmaxf(c1o[o * 64 + 2 * j2], c1o[o * 64 + 2 * j2 + 1]);
    }
    __syncthreads();
    // conv2 (16->32, k=5, valid) + relu, flat index = o*28 + t
    #pragma unroll
    for (int it = 0; it < 2; it++) {
        int j = tid + it * NTH;
        if (j < 896) {
            int o = j / 28, t = j - o * 28;
            const float* wo = Wsm + C2W_OFF + o * 80;
            const float* pb = pool + t;
            float acc = Wsm[C2B_OFF + o];
            #pragma unroll
            for (int i = 0; i < 16; i++) {
                #pragma unroll
                for (int kk = 0; kk < 5; kk++)
                    acc += pb[i * 32 + kk] * wo[i * 5 + kk];
            }
            flat[j] = fmaxf(acc, 0.0f);
        }
    }
    __syncthreads();

    // dense 896 -> 128, relu  (warp per output row)
    for (int h = wid; h < 128; h += NW) {
        const float* wr = d1w + (size_t)h * 896;
        float acc = 0.0f;
        for (int m = lane; m < 896; m += 32) acc += flat[m] * wr[m];
        #pragma unroll
        for (int o = 16; o > 0; o >>= 1) acc += __shfl_down_sync(0xffffffffu, acc, o);
        if (lane == 0) hid[h] = fmaxf(acc + d1b[h], 0.0f);
    }
    __syncthreads();

    // dense 128 -> 10
    if (wid < 10) {
        const float* wr = d2w + wid * 128;
        float acc = 0.0f;
        for (int m = lane; m < 128; m += 32) acc += hid[m] * wr[m];
        #pragma unroll
        for (int o = 16; o > 0; o >>= 1) acc += __shfl_down_sync(0xffffffffu, acc, o);
        if (lane == 0) out[g * 10 + wid] = acc + d2b[wid];
    }
}

extern "C" void kernel_launch(void* const* d_in, const int* in_sizes, int n_in,
                              void* d_out, int out_size)
{
    (void)in_sizes; (void)n_in; (void)out_size;
    const float* x    = (const float*)d_in[0];
    const float* W0   = (const float*)d_in[1];
    const float* b0   = (const float*)d_in[2];
    const float* W1   = (const float*)d_in[3];
    const float* b1   = (const float*)d_in[4];
    const float* W2   = (const float*)d_in[5];
    const float* b2   = (const float*)d_in[6];
    const float* W3   = (const float*)d_in[7];
    const float* b3   = (const float*)d_in[8];
    const float* c1w  = (const float*)d_in[9];
    const float* c1b  = (const float*)d_in[10];
    const float* c2w  = (const float*)d_in[11];
    const float* c2b  = (const float*)d_in[12];
    const float* d1w  = (const float*)d_in[13];
    const float* d1b  = (const float*)d_in[14];
    const float* d2w  = (const float*)d_in[15];
    const float* d2b  = (const float*)d_in[16];
    const int*   esrc = (const int*)d_in[17];
    const int*   edst = (const int*)d_in[18];
    float* out = (float*)d_out;

    cudaFuncSetAttribute(dgcnn_kernel,
                         cudaFuncAttributeMaxDynamicSharedMemorySize, SMEM_BYTES);
    dgcnn_kernel<<<BG, NTH, SMEM_BYTES>>>(x, W0, b0, W1, b1, W2, b2, W3, b3,
                                          c1w, c1b, c2w, c2b,
                                          d1w, d1b, d2w, d2b,
                                          esrc, edst, out);
}